// round 11
// baseline (speedup 1.0000x reference)
#include <cuda_runtime.h>
#include <math.h>

// ---------------- scratch (no allocation allowed) ----------------
#define NEL 16777216  // 16*64*128*128  == 16*256*64*64
__device__ float g_buf0[NEL];
__device__ float g_buf1[NEL];
__device__ float g_buf2[NEL];
__device__ float g_imap[262144];   // 16*128*128
__device__ float g_inc[262144];
__device__ float g_mean[256];
__device__ float g_rstd[256];

// ========== 3x3 conv, pad=1, Winograd F(2x2,3x3), co-block 8 ==========
// CTA: 256 threads; 32x32 spatial tile x 8 output channels.
// Thread (tx=tid&15, ty=tid>>4) owns ONE Winograd tile (2x2 outputs) per co.
// Accumulates in the transform domain: acc[8][16] (+= t[k] * u[co][k]).
// Weights are Winograd-transformed (G g G^T) during smem staging.
// Per ci per thread: 32 FADD (B^T d B) + 8*16 FFMA  vs  8*36 direct.
// BNIN: fused BN+ReLU on input load (in-bounds only; padding stays 0).
// ADDDEP: epilogue writes addsrc + beta*(conv+bias) (fuses dep + beta*fn).
// grid: (W/32, H/32, B * Cout/8)
template<int CIN, bool BNIN, bool ADDDEP>
__global__ void __launch_bounds__(256, 1)
wconv3x3(const float* __restrict__ in, const float* __restrict__ wt,
         const float* __restrict__ bias, float* __restrict__ out,
         const float* __restrict__ bng, const float* __restrict__ bnbe,
         const float* __restrict__ addsrc, const float* __restrict__ betap,
         int Cout, int H, int W) {
    constexpr int CICH = 32;
    __shared__ __align__(16) float tile[2][34 * 36];
    __shared__ __align__(16) float usm[CICH * 8 * 16];   // transformed weights
    const int tid = threadIdx.x;
    const int tx = tid & 15, ty = tid >> 4;
    const int groups = Cout >> 3;
    const int cog = blockIdx.z % groups;
    const int n   = blockIdx.z / groups;
    const int co0 = cog << 3;
    const int oy0 = blockIdx.y * 32, ox0 = blockIdx.x * 32;

    // precompute tile-load coords (no div/mod inside the ci loop)
    int soff[5], goff[5];
    bool gval[5], sval[5];
    #pragma unroll
    for (int k = 0; k < 5; k++) {
        int e = tid + k * 256;
        int ly = e / 34, lx = e - ly * 34;
        int gy = oy0 + ly - 1, gx = ox0 + lx - 1;
        sval[k] = (e < 34 * 34);
        gval[k] = sval[k] && gy >= 0 && gy < H && gx >= 0 && gx < W;
        soff[k] = ly * 36 + lx;
        goff[k] = gval[k] ? gy * W + gx : 0;
    }

    const float* inb = in + (size_t)n * CIN * H * W;

    // prologue: load ci=0 into tile[0] (BN only on in-bounds pixels)
    {
        float sc = 1.f, sh = 0.f;
        if (BNIN) { float s = g_rstd[0] * bng[0]; sc = s; sh = bnbe[0] - g_mean[0] * s; }
        #pragma unroll
        for (int k = 0; k < 5; k++) {
            float v = 0.f;
            if (gval[k]) {
                v = inb[goff[k]];
                if (BNIN) v = fmaxf(fmaf(v, sc, sh), 0.f);
            }
            if (sval[k]) tile[0][soff[k]] = v;
        }
    }

    float acc[8][16];
    #pragma unroll
    for (int c = 0; c < 8; c++)
        #pragma unroll
        for (int j = 0; j < 16; j++) acc[c][j] = 0.f;

    for (int ci = 0; ci < CIN; ci++) {
        const int cc = ci & (CICH - 1);
        if (cc == 0) {
            __syncthreads();   // previous chunk's compute done before usm overwrite
            // stage + Winograd-transform weights: thread = one (ci-offset, co) pair
            const int c  = tid >> 3;    // 0..31
            const int co = tid & 7;     // 0..7
            const float* gp = &wt[(((size_t)(co0 + co)) * CIN + (ci + c)) * 9];
            float g[9];
            #pragma unroll
            for (int j = 0; j < 9; j++) g[j] = gp[j];
            // q = G g  (4x3)
            float q[4][3];
            #pragma unroll
            for (int j = 0; j < 3; j++) {
                q[0][j] = g[j];
                q[1][j] = 0.5f * (g[j] + g[3 + j] + g[6 + j]);
                q[2][j] = 0.5f * (g[j] - g[3 + j] + g[6 + j]);
                q[3][j] = g[6 + j];
            }
            // u = q G^T (4x4)
            float* ud = &usm[tid * 16];
            #pragma unroll
            for (int i = 0; i < 4; i++) {
                ud[i * 4 + 0] = q[i][0];
                ud[i * 4 + 1] = 0.5f * (q[i][0] + q[i][1] + q[i][2]);
                ud[i * 4 + 2] = 0.5f * (q[i][0] - q[i][1] + q[i][2]);
                ud[i * 4 + 3] = q[i][2];
            }
        }
        __syncthreads();       // tile[ci&1] stored & usm ready; prev compute done
        const int buf = ci & 1;

        // prefetch next input channel into registers (overlaps compute)
        float pv[5];
        if (ci + 1 < CIN) {
            const float* ip = inb + (size_t)(ci + 1) * H * W;
            float sc = 1.f, sh = 0.f;
            if (BNIN) {
                float s = g_rstd[ci + 1] * bng[ci + 1];
                sc = s; sh = bnbe[ci + 1] - g_mean[ci + 1] * s;
            }
            #pragma unroll
            for (int k = 0; k < 5; k++) {
                float v = 0.f;
                if (gval[k]) {
                    v = ip[goff[k]];
                    if (BNIN) v = fmaxf(fmaf(v, sc, sh), 0.f);
                }
                pv[k] = v;
            }
        }

        // load this thread's 4x4 input patch
        float iv[4][4];
        #pragma unroll
        for (int r = 0; r < 4; r++) {
            const float* rp = &tile[buf][(ty * 2 + r) * 36 + tx * 2];
            float2 a = *(const float2*)rp;
            float2 b = *(const float2*)(rp + 2);
            iv[r][0] = a.x; iv[r][1] = a.y; iv[r][2] = b.x; iv[r][3] = b.y;
        }

        // t = B^T d B  (32 FADD)
        float wv[16], t[16];
        #pragma unroll
        for (int j = 0; j < 4; j++) {
            wv[0 * 4 + j] = iv[0][j] - iv[2][j];
            wv[1 * 4 + j] = iv[1][j] + iv[2][j];
            wv[2 * 4 + j] = iv[2][j] - iv[1][j];
            wv[3 * 4 + j] = iv[1][j] - iv[3][j];
        }
        #pragma unroll
        for (int i = 0; i < 4; i++) {
            t[i * 4 + 0] = wv[i * 4 + 0] - wv[i * 4 + 2];
            t[i * 4 + 1] = wv[i * 4 + 1] + wv[i * 4 + 2];
            t[i * 4 + 2] = wv[i * 4 + 2] - wv[i * 4 + 1];
            t[i * 4 + 3] = wv[i * 4 + 1] - wv[i * 4 + 3];
        }

        // acc[co][k] += t[k] * u[co][k]   (broadcast LDS.128 x4 per co)
        const float4* ub = (const float4*)&usm[cc * 128];
        #pragma unroll
        for (int co = 0; co < 8; co++) {
            float4 u0 = ub[co * 4 + 0], u1 = ub[co * 4 + 1];
            float4 u2 = ub[co * 4 + 2], u3 = ub[co * 4 + 3];
            acc[co][0]  = fmaf(t[0],  u0.x, acc[co][0]);
            acc[co][1]  = fmaf(t[1],  u0.y, acc[co][1]);
            acc[co][2]  = fmaf(t[2],  u0.z, acc[co][2]);
            acc[co][3]  = fmaf(t[3],  u0.w, acc[co][3]);
            acc[co][4]  = fmaf(t[4],  u1.x, acc[co][4]);
            acc[co][5]  = fmaf(t[5],  u1.y, acc[co][5]);
            acc[co][6]  = fmaf(t[6],  u1.z, acc[co][6]);
            acc[co][7]  = fmaf(t[7],  u1.w, acc[co][7]);
            acc[co][8]  = fmaf(t[8],  u2.x, acc[co][8]);
            acc[co][9]  = fmaf(t[9],  u2.y, acc[co][9]);
            acc[co][10] = fmaf(t[10], u2.z, acc[co][10]);
            acc[co][11] = fmaf(t[11], u2.w, acc[co][11]);
            acc[co][12] = fmaf(t[12], u3.x, acc[co][12]);
            acc[co][13] = fmaf(t[13], u3.y, acc[co][13]);
            acc[co][14] = fmaf(t[14], u3.z, acc[co][14]);
            acc[co][15] = fmaf(t[15], u3.w, acc[co][15]);
        }

        // commit prefetched tile
        if (ci + 1 < CIN) {
            #pragma unroll
            for (int k = 0; k < 5; k++)
                if (sval[k]) tile[buf ^ 1][soff[k]] = pv[k];
        }
    }

    // epilogue: Y = A^T m A, add bias (+ optional dep + beta*fn fusion)
    const float beta = ADDDEP ? betap[0] : 0.f;
    #pragma unroll
    for (int co = 0; co < 8; co++) {
        const float* m = acc[co];
        float s00 = m[0] + m[4] + m[8],   s01 = m[1] + m[5] + m[9];
        float s02 = m[2] + m[6] + m[10],  s03 = m[3] + m[7] + m[11];
        float s10 = m[4] - m[8] - m[12],  s11 = m[5] - m[9] - m[13];
        float s12 = m[6] - m[10] - m[14], s13 = m[7] - m[11] - m[15];
        float bv = bias[co0 + co];
        float y00 = s00 + s01 + s02 + bv, y01 = s01 - s02 - s03 + bv;
        float y10 = s10 + s11 + s12 + bv, y11 = s11 - s12 - s13 + bv;
        size_t cb = ((size_t)n * Cout + co0 + co) * H * W;
        size_t o0 = cb + (size_t)(oy0 + ty * 2) * W + ox0 + tx * 2;
        size_t o1 = o0 + W;
        if (ADDDEP) {
            float2 d0 = *(const float2*)&addsrc[o0];
            float2 d1 = *(const float2*)&addsrc[o1];
            *(float2*)&out[o0] = make_float2(fmaf(beta, y00, d0.x), fmaf(beta, y01, d0.y));
            *(float2*)&out[o1] = make_float2(fmaf(beta, y10, d1.x), fmaf(beta, y11, d1.y));
        } else {
            *(float2*)&out[o0] = make_float2(y00, y01);
            *(float2*)&out[o1] = make_float2(y10, y11);
        }
    }
}

// ---------------- BN batch statistics (one block per channel) ----------------
__global__ void bn_stats_k(const float* __restrict__ x, int C, int HW, int Bn) {
    const int c = blockIdx.x;
    const int N = Bn * HW;
    float s = 0.f, s2 = 0.f;
    for (int i = threadIdx.x; i < N; i += blockDim.x) {
        int n = i / HW, j = i - n * HW;
        float v = x[((size_t)n * C + c) * HW + j];
        s += v; s2 += v * v;
    }
    __shared__ float sh[256], sh2[256];
    sh[threadIdx.x] = s; sh2[threadIdx.x] = s2;
    __syncthreads();
    for (int o = 128; o > 0; o >>= 1) {
        if (threadIdx.x < o) { sh[threadIdx.x] += sh[threadIdx.x + o]; sh2[threadIdx.x] += sh2[threadIdx.x + o]; }
        __syncthreads();
    }
    if (threadIdx.x == 0) {
        float m = sh[0] / (float)N;
        float var = sh2[0] / (float)N - m * m;
        g_mean[c] = m;
        g_rstd[c] = rsqrtf(var + 1e-5f);
    }
}

// ---------------- BN apply + ReLU + PixelShuffle(2) ----------------
__global__ void bn_relu_ps_k(const float* __restrict__ y, const float* __restrict__ g,
                             const float* __restrict__ be, float* __restrict__ dep) {
    int idx = blockIdx.x * 256 + threadIdx.x;   // 0 .. 16M
    int X = idx & 127;
    int Y = (idx >> 7) & 127;
    int c = (idx >> 14) & 63;
    int n = idx >> 20;
    int cy = c * 4 + (Y & 1) * 2 + (X & 1);
    float v = y[(((size_t)n * 256 + cy) * 64 + (Y >> 1)) * 64 + (X >> 1)];
    v = (v - g_mean[cy]) * g_rstd[cy] * g[cy] + be[cy];
    dep[idx] = fmaxf(v, 0.f);
}

// ---------------- BN apply + ReLU (src -> dst) ----------------
__global__ void bn_relu_out_k(const float* __restrict__ x, const float* __restrict__ g,
                              const float* __restrict__ be, float* __restrict__ dst) {
    int idx = blockIdx.x * 256 + threadIdx.x;
    int c = (idx >> 14) & 63;    // HW = 16384, C = 64
    float v = x[idx];
    v = (v - g_mean[c]) * g_rstd[c] * g[c] + be[c];
    dst[idx] = fmaxf(v, 0.f);
}

// ---------------- bilinear x2 (align_corners) + sigmoid ----------------
__global__ void up_sig_k(const float* __restrict__ in) {
    int idx = blockIdx.x * 256 + threadIdx.x;   // 16*128*128
    int X = idx & 127, Y = (idx >> 7) & 127, n = idx >> 14;
    const float sc = 63.0f / 127.0f;
    float yy = Y * sc, xx = X * sc;
    int y0 = (int)floorf(yy); float wy = yy - (float)y0; int y1 = min(y0 + 1, 63);
    int x0 = (int)floorf(xx); float wx = xx - (float)x0; int x1 = min(x0 + 1, 63);
    const float* p = in + n * 4096;
    float r0 = p[y0 * 64 + x0] * (1.f - wx) + p[y0 * 64 + x1] * wx;
    float r1 = p[y1 * 64 + x0] * (1.f - wx) + p[y1 * 64 + x1] * wx;
    float v = r0 * (1.f - wy) + r1 * wy;
    g_imap[idx] = 1.f / (1.f + expf(-v));
}

// ---------------- increase_map = dilate3x3(imap) - imap ----------------
__global__ void inc_k() {
    int idx = blockIdx.x * 256 + threadIdx.x;   // 16*128*128
    int X = idx & 127, Y = (idx >> 7) & 127, n = idx >> 14;
    const float* p = g_imap + (n << 14);
    float m = -1e30f;
    #pragma unroll
    for (int dy = -1; dy <= 1; dy++) {
        int y = Y + dy;
        if (y < 0 || y > 127) continue;
        #pragma unroll
        for (int dx = -1; dx <= 1; dx++) {
            int x = X + dx;
            if (x < 0 || x > 127) continue;
            m = fmaxf(m, p[y * 128 + x]);
        }
    }
    g_inc[idx] = m - p[Y * 128 + X];
}

// ---------------- b_feature = cur_x * increase_map ----------------
__global__ void mult_k(const float* __restrict__ cur) {
    int idx = blockIdx.x * 256 + threadIdx.x;   // 16M
    int sp = idx & 16383;
    int n = idx >> 20;
    g_buf2[idx] = cur[idx] * g_inc[(n << 14) | sp];
}

// ---------------- 7x7 conv, Cin=64 -> 1, pad=3 ----------------
__global__ void conv7x7_k(const float* __restrict__ in, const float* __restrict__ wt,
                          const float* __restrict__ bias, float* __restrict__ out) {
    __shared__ float tile[22][22];
    __shared__ float wsm[64 * 49];
    const int n = blockIdx.z;
    const int tid = threadIdx.y * 16 + threadIdx.x;
    for (int i = tid; i < 64 * 49; i += 256) wsm[i] = wt[i];
    const int oy0 = blockIdx.y * 16, ox0 = blockIdx.x * 16;
    float acc = 0.f;
    for (int ci = 0; ci < 64; ci++) {
        __syncthreads();
        const float* ip = in + ((size_t)n * 64 + ci) * 16384;
        for (int i = tid; i < 22 * 22; i += 256) {
            int ly = i / 22, lx = i % 22;
            int gy = oy0 + ly - 3, gx = ox0 + lx - 3;
            float v = 0.f;
            if (gy >= 0 && gy < 128 && gx >= 0 && gx < 128) v = ip[gy * 128 + gx];
            tile[ly][lx] = v;
        }
        __syncthreads();
        const float* wp = &wsm[ci * 49];
        #pragma unroll
        for (int dy = 0; dy < 7; dy++)
            #pragma unroll
            for (int dx = 0; dx < 7; dx++)
                acc = fmaf(tile[threadIdx.y + dy][threadIdx.x + dx], wp[dy * 7 + dx], acc);
    }
    out[((size_t)n * 128 + oy0 + threadIdx.y) * 128 + ox0 + threadIdx.x] = acc + bias[0];
}

// ---------------- launch ----------------
extern "C" void kernel_launch(void* const* d_in, const int* in_sizes, int n_in,
                              void* d_out, int out_size) {
    static float *buf0 = nullptr, *buf1 = nullptr, *buf2 = nullptr;
    if (!buf0) {
        cudaGetSymbolAddress((void**)&buf0, g_buf0);
        cudaGetSymbolAddress((void**)&buf1, g_buf1);
        cudaGetSymbolAddress((void**)&buf2, g_buf2);
    }
    const float* cur_x  = (const float*)d_in[0];
    const float* dep_x  = (const float*)d_in[1];
    const float* in_map = (const float*)d_in[2];
    const float* up_w   = (const float*)d_in[3];
    const float* up_b   = (const float*)d_in[4];
    const float* up_g   = (const float*)d_in[5];
    const float* up_be  = (const float*)d_in[6];
    const float* conv2_w = (const float*)d_in[7];
    const float* conv2_b = (const float*)d_in[8];
    const float* beta   = (const float*)d_in[9];
    const float* d1_w = (const float*)d_in[10], *d1_b = (const float*)d_in[11];
    const float* d1_g = (const float*)d_in[12], *d1_be = (const float*)d_in[13];
    const float* d2_w = (const float*)d_in[14], *d2_b = (const float*)d_in[15];
    const float* d2_g = (const float*)d_in[16], *d2_be = (const float*)d_in[17];
    const float* d3_w = (const float*)d_in[18], *d3_b = (const float*)d_in[19];
    const float* d3_g = (const float*)d_in[20], *d3_be = (const float*)d_in[21];
    const float* out_w = (const float*)d_in[22], *out_b = (const float*)d_in[23];

    float* r_out = (float*)d_out;               // [16,64,128,128]
    float* map_out = (float*)d_out + NEL;       // [16,1,128,128]

    dim3 gUp(2, 2, 16 * 32);      // 64x64, 32x32 tiles, Cout=256 -> 32 groups
    dim3 gD(4, 4, 16 * 8);        // 128x128, 32x32 tiles, Cout=64 -> 8 groups
    const int EW = NEL / 256;     // elementwise grid (65536)

    // up path: conv(C2->4C1) + BN + ReLU + pixel shuffle
    wconv3x3<128, false, false><<<gUp, 256>>>(dep_x, up_w, up_b, buf0,
                                              nullptr, nullptr, nullptr, nullptr, 256, 64, 64);
    bn_stats_k<<<256, 256>>>(buf0, 256, 4096, 16);
    bn_relu_ps_k<<<EW, 256>>>(buf0, up_g, up_be, buf1);   // buf1 = dep

    // attention-map path
    up_sig_k<<<1024, 256>>>(in_map);
    inc_k<<<1024, 256>>>();
    mult_k<<<EW, 256>>>(cur_x);                            // buf2 = b_feature

    // conv2 + fused (dep + beta*fn): buf0 = buf1 + beta*conv(buf2)
    wconv3x3<64, false, true><<<gD, 256>>>(buf2, conv2_w, conv2_b, buf0,
                                           nullptr, nullptr, buf1, beta, 64, 128, 128);

    // d1: conv(raw) -> buf2 ; stats on buf2
    wconv3x3<64, false, false><<<gD, 256>>>(buf0, d1_w, d1_b, buf2,
                                            nullptr, nullptr, nullptr, nullptr, 64, 128, 128);
    bn_stats_k<<<64, 256>>>(buf2, 64, 16384, 16);
    // d2: conv with fused BN1+ReLU on input -> buf1 ; stats on buf1
    wconv3x3<64, true, false><<<gD, 256>>>(buf2, d2_w, d2_b, buf1,
                                           d1_g, d1_be, nullptr, nullptr, 64, 128, 128);
    bn_stats_k<<<64, 256>>>(buf1, 64, 16384, 16);
    // d3: conv with fused BN2+ReLU on input -> buf2 ; stats on buf2
    wconv3x3<64, true, false><<<gD, 256>>>(buf1, d3_w, d3_b, buf2,
                                           d2_g, d2_be, nullptr, nullptr, 64, 128, 128);
    bn_stats_k<<<64, 256>>>(buf2, 64, 16384, 16);
    // r = BN3 + ReLU -> output region
    bn_relu_out_k<<<EW, 256>>>(buf2, d3_g, d3_be, r_out);

    // output_map = conv7x7(r)
    conv7x7_k<<<dim3(8, 8, 16), dim3(16, 16)>>>(r_out, out_w, out_b, map_out);
}

// round 13
// speedup vs baseline: 1.6655x; 1.6655x over previous
#include <cuda_runtime.h>
#include <cuda_bf16.h>
#include <math.h>

// ---------------- scratch (no allocation allowed) ----------------
#define NEL 16777216  // 16*64*128*128  == 16*256*64*64
__device__ float g_buf0[NEL];
__device__ float g_buf1[NEL];
__device__ float g_buf2[NEL];
__device__ float g_imap[262144];   // 16*128*128
__device__ float g_inc[262144];
__device__ float g_mean[256];
__device__ float g_rstd[256];

typedef unsigned int u32;

// smem byte offsets for tconv3x3 (dynamic smem)
#define A_HI 0
#define A_LO 18944                 // 130*72*2 = 18720 rounded up
#define B_HI 37888
#define B_LO 65536                 // 3*64*72*2 = 27648 each
#define T_SMEM 93184
#define AST 72                     // bf16 stride (rows)
#define EPST 68                    // f32 stride for epilogue tile

__device__ __forceinline__ void mma16816(float* d, const u32* a, const u32* b) {
    asm volatile(
        "mma.sync.aligned.m16n8k16.row.col.f32.bf16.bf16.f32 "
        "{%0,%1,%2,%3}, {%4,%5,%6,%7}, {%8,%9}, {%0,%1,%2,%3};"
        : "+f"(d[0]), "+f"(d[1]), "+f"(d[2]), "+f"(d[3])
        : "r"(a[0]), "r"(a[1]), "r"(a[2]), "r"(a[3]), "r"(b[0]), "r"(b[1]));
}

// ========== mma.sync 3x3 conv, C=64->64, H=W=128, pad=1, bf16 hi/lo split ==========
// CTA = one output row y of batch n: D[128 px][64 co].
// A smem: [row 0..129][ci 64] bf16 (rows 0,129 = zero pad); tap dx = row offset.
// B smem per dy: [dx*64+co][ci 64] bf16. 3 split passes: AhBh + AhBl + AlBh.
// 8 warps: warp (wm=w&3, wn=w>>2) owns output tile [wm*32..+32) x [wn*32..+32).
// BNIN: BN+ReLU fused into input staging. ADDDEP: out = addsrc + beta*(conv+bias).
template<bool BNIN, bool ADDDEP>
__global__ void __launch_bounds__(256, 2)
tconv3x3(const float* __restrict__ in, const float* __restrict__ wt,
         const float* __restrict__ bias_, float* __restrict__ out,
         const float* __restrict__ bng, const float* __restrict__ bnbe,
         const float* __restrict__ addsrc, const float* __restrict__ betap) {
    extern __shared__ char smem[];
    __nv_bfloat16* Ah = (__nv_bfloat16*)(smem + A_HI);
    __nv_bfloat16* Al = (__nv_bfloat16*)(smem + A_LO);
    __nv_bfloat16* Bh = (__nv_bfloat16*)(smem + B_HI);
    __nv_bfloat16* Bl = (__nv_bfloat16*)(smem + B_LO);
    const int tid = threadIdx.x;
    const int w = tid >> 5, lane = tid & 31;
    const int wm = w & 3, wn = w >> 2;
    const int g = lane >> 2, t = lane & 3;
    const int y = blockIdx.x, n = blockIdx.y;

    // zero pad rows 0 and 129 of A (hi+lo), once
    if (tid < 128) {
        int b = tid >> 6, r = (tid >> 5) & 1, wd = tid & 31;
        __nv_bfloat16* dst = b ? Al : Ah;
        *(u32*)&dst[(r ? 129 : 0) * AST + wd * 2] = 0u;
    }

    float acc[2][4][4];
    #pragma unroll
    for (int mi = 0; mi < 2; mi++)
        #pragma unroll
        for (int ni = 0; ni < 4; ni++)
            #pragma unroll
            for (int j = 0; j < 4; j++) acc[mi][ni][j] = 0.f;

    #pragma unroll
    for (int dy = 0; dy < 3; dy++) {
        const int u = y + dy - 1;
        if (u < 0 || u > 127) continue;
        __syncthreads();   // prev compute (or pad zeroing) done before overwrite

        // ---- stage A: input row u, 64 ci x 128 x ----
        const float* ip = in + (((size_t)n * 64) * 128 + u) * 128;
        for (int it = tid; it < 8192; it += 256) {
            int ci = it >> 7, xx = it & 127;
            float v = ip[(size_t)ci * 16384 + xx];
            if (BNIN) {
                float s = g_rstd[ci] * bng[ci];
                v = fmaxf(fmaf(v, s, bnbe[ci] - g_mean[ci] * s), 0.f);
            }
            __nv_bfloat16 hb = __float2bfloat16_rn(v);
            float h = __bfloat162float(hb);
            Ah[(xx + 1) * AST + ci] = hb;
            Al[(xx + 1) * AST + ci] = __float2bfloat16_rn(v - h);
        }
        // ---- stage B: weights for this dy: [dx*64+co][ci] ----
        for (int it = tid; it < 12288; it += 256) {
            int co = it / 192, r = it - co * 192;
            int dx = r >> 6, ci = r & 63;
            float wv = wt[(((size_t)co * 64 + ci) * 3 + dy) * 3 + dx];
            __nv_bfloat16 hb = __float2bfloat16_rn(wv);
            float h = __bfloat162float(hb);
            Bh[(dx * 64 + co) * AST + ci] = hb;
            Bl[(dx * 64 + co) * AST + ci] = __float2bfloat16_rn(wv - h);
        }
        __syncthreads();

        // ---- compute: 3 dx x 4 ksteps x (2 m-atoms x 4 n-atoms) x 3 splits ----
        #pragma unroll
        for (int dx = 0; dx < 3; dx++) {
            const int ar0 = dx + wm * 32 + g;
            const int bn0 = dx * 64 + wn * 32 + g;
            #pragma unroll
            for (int ks = 0; ks < 4; ks++) {
                const int k0 = ks * 16 + t * 2;
                u32 ah[2][4], al[2][4];
                #pragma unroll
                for (int mi = 0; mi < 2; mi++) {
                    int r0 = ar0 + mi * 16;
                    ah[mi][0] = *(const u32*)&Ah[r0 * AST + k0];
                    ah[mi][1] = *(const u32*)&Ah[(r0 + 8) * AST + k0];
                    ah[mi][2] = *(const u32*)&Ah[r0 * AST + k0 + 8];
                    ah[mi][3] = *(const u32*)&Ah[(r0 + 8) * AST + k0 + 8];
                    al[mi][0] = *(const u32*)&Al[r0 * AST + k0];
                    al[mi][1] = *(const u32*)&Al[(r0 + 8) * AST + k0];
                    al[mi][2] = *(const u32*)&Al[r0 * AST + k0 + 8];
                    al[mi][3] = *(const u32*)&Al[(r0 + 8) * AST + k0 + 8];
                }
                u32 bh[4][2], bl[4][2];
                #pragma unroll
                for (int ni = 0; ni < 4; ni++) {
                    int br = bn0 + ni * 8;
                    bh[ni][0] = *(const u32*)&Bh[br * AST + k0];
                    bh[ni][1] = *(const u32*)&Bh[br * AST + k0 + 8];
                    bl[ni][0] = *(const u32*)&Bl[br * AST + k0];
                    bl[ni][1] = *(const u32*)&Bl[br * AST + k0 + 8];
                }
                #pragma unroll
                for (int mi = 0; mi < 2; mi++)
                    #pragma unroll
                    for (int ni = 0; ni < 4; ni++) {
                        mma16816(acc[mi][ni], ah[mi], bh[ni]);
                        mma16816(acc[mi][ni], ah[mi], bl[ni]);
                        mma16816(acc[mi][ni], al[mi], bh[ni]);
                    }
            }
        }
    }

    // ---- epilogue: transpose through smem, coalesced STG ----
    __syncthreads();
    float* ep = (float*)smem;
    #pragma unroll
    for (int mi = 0; mi < 2; mi++)
        #pragma unroll
        for (int ni = 0; ni < 4; ni++) {
            int x = wm * 32 + mi * 16 + g;
            int co = wn * 32 + ni * 8 + 2 * t;
            ep[x * EPST + co]           = acc[mi][ni][0];
            ep[x * EPST + co + 1]       = acc[mi][ni][1];
            ep[(x + 8) * EPST + co]     = acc[mi][ni][2];
            ep[(x + 8) * EPST + co + 1] = acc[mi][ni][3];
        }
    __syncthreads();
    const float beta = ADDDEP ? betap[0] : 0.f;
    for (int it = tid; it < 8192; it += 256) {
        int co = it >> 7, x = it & 127;
        float v = ep[x * EPST + co] + bias_[co];
        size_t o = (((size_t)n * 64 + co) * 128 + y) * 128 + x;
        if (ADDDEP) v = fmaf(beta, v, addsrc[o]);
        out[o] = v;
    }
}

// ============ scalar 3x3 conv (R9, known good) — used for the up-conv ============
template<int CIN, bool BNIN>
__global__ void __launch_bounds__(256, 2)
conv3x3mc(const float* __restrict__ in, const float* __restrict__ wt,
          const float* __restrict__ bias, float* __restrict__ out,
          const float* __restrict__ bng, const float* __restrict__ bnbe,
          int Cout, int H, int W) {
    constexpr int CICHUNK = 32;
    __shared__ __align__(16) float tile[2][34 * 36];
    __shared__ __align__(16) float wsm[CICHUNK * 16 * 12];
    const int tid = threadIdx.x;
    const int tx = tid & 15, ty = tid >> 4;
    const int groups = Cout >> 4;
    const int cog = blockIdx.z % groups;
    const int n   = blockIdx.z / groups;
    const int co0 = cog << 4;
    const int oy0 = blockIdx.y * 32, ox0 = blockIdx.x * 32;

    int soff[5], goff[5];
    bool gval[5], sval[5];
    #pragma unroll
    for (int k = 0; k < 5; k++) {
        int e = tid + k * 256;
        int ly = e / 34, lx = e - ly * 34;
        int gy = oy0 + ly - 1, gx = ox0 + lx - 1;
        sval[k] = (e < 34 * 34);
        gval[k] = sval[k] && gy >= 0 && gy < H && gx >= 0 && gx < W;
        soff[k] = ly * 36 + lx;
        goff[k] = gval[k] ? gy * W + gx : 0;
    }
    const float* inb = in + (size_t)n * CIN * H * W;
    {
        float sc = 1.f, sh = 0.f;
        if (BNIN) { float s = g_rstd[0] * bng[0]; sc = s; sh = bnbe[0] - g_mean[0] * s; }
        #pragma unroll
        for (int k = 0; k < 5; k++) {
            float v = 0.f;
            if (gval[k]) {
                v = inb[goff[k]];
                if (BNIN) v = fmaxf(fmaf(v, sc, sh), 0.f);
            }
            if (sval[k]) tile[0][soff[k]] = v;
        }
    }
    float acc[16][4];
    #pragma unroll
    for (int c = 0; c < 16; c++)
        #pragma unroll
        for (int j = 0; j < 4; j++) acc[c][j] = 0.f;

    for (int ci = 0; ci < CIN; ci++) {
        const int cc = ci & (CICHUNK - 1);
        if (cc == 0) {
            __syncthreads();
            #pragma unroll 2
            for (int i = tid; i < CICHUNK * 16 * 9; i += 256) {
                int c = i / 144; int r = i - c * 144; int co = r / 9; int j = r - co * 9;
                wsm[(c * 16 + co) * 12 + j] =
                    wt[(((size_t)(co0 + co)) * CIN + (ci + c)) * 9 + j];
            }
        }
        __syncthreads();
        const int buf = ci & 1;
        float pv[5];
        if (ci + 1 < CIN) {
            const float* ip = inb + (size_t)(ci + 1) * H * W;
            float sc = 1.f, sh = 0.f;
            if (BNIN) {
                float s = g_rstd[ci + 1] * bng[ci + 1];
                sc = s; sh = bnbe[ci + 1] - g_mean[ci + 1] * s;
            }
            #pragma unroll
            for (int k = 0; k < 5; k++) {
                float v = 0.f;
                if (gval[k]) {
                    v = ip[goff[k]];
                    if (BNIN) v = fmaxf(fmaf(v, sc, sh), 0.f);
                }
                pv[k] = v;
            }
        }
        float iv[4][4];
        #pragma unroll
        for (int r = 0; r < 4; r++) {
            const float* rp = &tile[buf][(ty * 2 + r) * 36 + tx * 2];
            float2 a = *(const float2*)rp;
            float2 b = *(const float2*)(rp + 2);
            iv[r][0] = a.x; iv[r][1] = a.y; iv[r][2] = b.x; iv[r][3] = b.y;
        }
        const float* wb = &wsm[cc * 192];
        #pragma unroll
        for (int co = 0; co < 16; co++) {
            float4 wa = *(const float4*)&wb[co * 12];
            float4 wc = *(const float4*)&wb[co * 12 + 4];
            float w8 = wb[co * 12 + 8];
            float w[9] = {wa.x, wa.y, wa.z, wa.w, wc.x, wc.y, wc.z, wc.w, w8};
            #pragma unroll
            for (int r2 = 0; r2 < 2; r2++)
                #pragma unroll
                for (int c2 = 0; c2 < 2; c2++) {
                    float s = acc[co][r2 * 2 + c2];
                    #pragma unroll
                    for (int dyy = 0; dyy < 3; dyy++)
                        #pragma unroll
                        for (int dxx = 0; dxx < 3; dxx++)
                            s = fmaf(iv[r2 + dyy][c2 + dxx], w[dyy * 3 + dxx], s);
                    acc[co][r2 * 2 + c2] = s;
                }
        }
        if (ci + 1 < CIN) {
            #pragma unroll
            for (int k = 0; k < 5; k++)
                if (sval[k]) tile[buf ^ 1][soff[k]] = pv[k];
        }
    }
    #pragma unroll
    for (int co = 0; co < 16; co++) {
        float bv = bias[co0 + co];
        size_t cb = ((size_t)n * Cout + co0 + co) * H * W;
        #pragma unroll
        for (int r2 = 0; r2 < 2; r2++) {
            int oy = oy0 + ty * 2 + r2;
            float2 o = make_float2(acc[co][r2 * 2] + bv, acc[co][r2 * 2 + 1] + bv);
            *(float2*)&out[cb + (size_t)oy * W + ox0 + tx * 2] = o;
        }
    }
}

// ---------------- BN batch statistics (one block per channel) ----------------
__global__ void bn_stats_k(const float* __restrict__ x, int C, int HW, int Bn) {
    const int c = blockIdx.x;
    const int N = Bn * HW;
    float s = 0.f, s2 = 0.f;
    for (int i = threadIdx.x; i < N; i += blockDim.x) {
        int n = i / HW, j = i - n * HW;
        float v = x[((size_t)n * C + c) * HW + j];
        s += v; s2 += v * v;
    }
    __shared__ float sh[256], sh2[256];
    sh[threadIdx.x] = s; sh2[threadIdx.x] = s2;
    __syncthreads();
    for (int o = 128; o > 0; o >>= 1) {
        if (threadIdx.x < o) { sh[threadIdx.x] += sh[threadIdx.x + o]; sh2[threadIdx.x] += sh2[threadIdx.x + o]; }
        __syncthreads();
    }
    if (threadIdx.x == 0) {
        float m = sh[0] / (float)N;
        float var = sh2[0] / (float)N - m * m;
        g_mean[c] = m;
        g_rstd[c] = rsqrtf(var + 1e-5f);
    }
}

// ---------------- BN apply + ReLU + PixelShuffle(2) ----------------
__global__ void bn_relu_ps_k(const float* __restrict__ y, const float* __restrict__ g,
                             const float* __restrict__ be, float* __restrict__ dep) {
    int idx = blockIdx.x * 256 + threadIdx.x;
    int X = idx & 127;
    int Y = (idx >> 7) & 127;
    int c = (idx >> 14) & 63;
    int n = idx >> 20;
    int cy = c * 4 + (Y & 1) * 2 + (X & 1);
    float v = y[(((size_t)n * 256 + cy) * 64 + (Y >> 1)) * 64 + (X >> 1)];
    v = (v - g_mean[cy]) * g_rstd[cy] * g[cy] + be[cy];
    dep[idx] = fmaxf(v, 0.f);
}

// ---------------- BN apply + ReLU (src -> dst) ----------------
__global__ void bn_relu_out_k(const float* __restrict__ x, const float* __restrict__ g,
                              const float* __restrict__ be, float* __restrict__ dst) {
    int idx = blockIdx.x * 256 + threadIdx.x;
    int c = (idx >> 14) & 63;
    float v = x[idx];
    v = (v - g_mean[c]) * g_rstd[c] * g[c] + be[c];
    dst[idx] = fmaxf(v, 0.f);
}

// ---------------- bilinear x2 (align_corners) + sigmoid ----------------
__global__ void up_sig_k(const float* __restrict__ in) {
    int idx = blockIdx.x * 256 + threadIdx.x;
    int X = idx & 127, Y = (idx >> 7) & 127, n = idx >> 14;
    const float sc = 63.0f / 127.0f;
    float yy = Y * sc, xx = X * sc;
    int y0 = (int)floorf(yy); float wy = yy - (float)y0; int y1 = min(y0 + 1, 63);
    int x0 = (int)floorf(xx); float wx = xx - (float)x0; int x1 = min(x0 + 1, 63);
    const float* p = in + n * 4096;
    float r0 = p[y0 * 64 + x0] * (1.f - wx) + p[y0 * 64 + x1] * wx;
    float r1 = p[y1 * 64 + x0] * (1.f - wx) + p[y1 * 64 + x1] * wx;
    float v = r0 * (1.f - wy) + r1 * wy;
    g_imap[idx] = 1.f / (1.f + expf(-v));
}

// ---------------- increase_map = dilate3x3(imap) - imap ----------------
__global__ void inc_k() {
    int idx = blockIdx.x * 256 + threadIdx.x;
    int X = idx & 127, Y = (idx >> 7) & 127, n = idx >> 14;
    const float* p = g_imap + (n << 14);
    float m = -1e30f;
    #pragma unroll
    for (int dy = -1; dy <= 1; dy++) {
        int y = Y + dy;
        if (y < 0 || y > 127) continue;
        #pragma unroll
        for (int dx = -1; dx <= 1; dx++) {
            int x = X + dx;
            if (x < 0 || x > 127) continue;
            m = fmaxf(m, p[y * 128 + x]);
        }
    }
    g_inc[idx] = m - p[Y * 128 + X];
}

// ---------------- b_feature = cur_x * increase_map ----------------
__global__ void mult_k(const float* __restrict__ cur) {
    int idx = blockIdx.x * 256 + threadIdx.x;
    int sp = idx & 16383;
    int n = idx >> 20;
    g_buf2[idx] = cur[idx] * g_inc[(n << 14) | sp];
}

// ---------------- 7x7 conv, Cin=64 -> 1, pad=3 ----------------
__global__ void conv7x7_k(const float* __restrict__ in, const float* __restrict__ wt,
                          const float* __restrict__ bias, float* __restrict__ out) {
    __shared__ float tile[22][22];
    __shared__ float wsm[64 * 49];
    const int n = blockIdx.z;
    const int tid = threadIdx.y * 16 + threadIdx.x;
    for (int i = tid; i < 64 * 49; i += 256) wsm[i] = wt[i];
    const int oy0 = blockIdx.y * 16, ox0 = blockIdx.x * 16;
    float acc = 0.f;
    for (int ci = 0; ci < 64; ci++) {
        __syncthreads();
        const float* ip = in + ((size_t)n * 64 + ci) * 16384;
        for (int i = tid; i < 22 * 22; i += 256) {
            int ly = i / 22, lx = i % 22;
            int gy = oy0 + ly - 3, gx = ox0 + lx - 3;
            float v = 0.f;
            if (gy >= 0 && gy < 128 && gx >= 0 && gx < 128) v = ip[gy * 128 + gx];
            tile[ly][lx] = v;
        }
        __syncthreads();
        const float* wp = &wsm[ci * 49];
        #pragma unroll
        for (int dy = 0; dy < 7; dy++)
            #pragma unroll
            for (int dx = 0; dx < 7; dx++)
                acc = fmaf(tile[threadIdx.y + dy][threadIdx.x + dx], wp[dy * 7 + dx], acc);
    }
    out[((size_t)n * 128 + oy0 + threadIdx.y) * 128 + ox0 + threadIdx.x] = acc + bias[0];
}

// ---------------- launch ----------------
extern "C" void kernel_launch(void* const* d_in, const int* in_sizes, int n_in,
                              void* d_out, int out_size) {
    static float *buf0 = nullptr, *buf1 = nullptr, *buf2 = nullptr;
    if (!buf0) {
        cudaGetSymbolAddress((void**)&buf0, g_buf0);
        cudaGetSymbolAddress((void**)&buf1, g_buf1);
        cudaGetSymbolAddress((void**)&buf2, g_buf2);
        cudaFuncSetAttribute(tconv3x3<false, true>,  cudaFuncAttributeMaxDynamicSharedMemorySize, T_SMEM);
        cudaFuncSetAttribute(tconv3x3<false, false>, cudaFuncAttributeMaxDynamicSharedMemorySize, T_SMEM);
        cudaFuncSetAttribute(tconv3x3<true,  false>, cudaFuncAttributeMaxDynamicSharedMemorySize, T_SMEM);
    }
    const float* cur_x  = (const float*)d_in[0];
    const float* dep_x  = (const float*)d_in[1];
    const float* in_map = (const float*)d_in[2];
    const float* up_w   = (const float*)d_in[3];
    const float* up_b   = (const float*)d_in[4];
    const float* up_g   = (const float*)d_in[5];
    const float* up_be  = (const float*)d_in[6];
    const float* conv2_w = (const float*)d_in[7];
    const float* conv2_b = (const float*)d_in[8];
    const float* beta   = (const float*)d_in[9];
    const float* d1_w = (const float*)d_in[10], *d1_b = (const float*)d_in[11];
    const float* d1_g = (const float*)d_in[12], *d1_be = (const float*)d_in[13];
    const float* d2_w = (const float*)d_in[14], *d2_b = (const float*)d_in[15];
    const float* d2_g = (const float*)d_in[16], *d2_be = (const float*)d_in[17];
    const float* d3_w = (const float*)d_in[18], *d3_b = (const float*)d_in[19];
    const float* d3_g = (const float*)d_in[20], *d3_be = (const float*)d_in[21];
    const float* out_w = (const float*)d_in[22], *out_b = (const float*)d_in[23];

    float* r_out = (float*)d_out;               // [16,64,128,128]
    float* map_out = (float*)d_out + NEL;       // [16,1,128,128]

    dim3 gUp(2, 2, 16 * 16);
    dim3 gT(128, 16);             // one output row per CTA
    const int EW = NEL / 256;

    // up path: conv(C2->4C1) + BN + ReLU + pixel shuffle  (scalar, known good)
    conv3x3mc<128, false><<<gUp, 256>>>(dep_x, up_w, up_b, buf0, nullptr, nullptr, 256, 64, 64);
    bn_stats_k<<<256, 256>>>(buf0, 256, 4096, 16);
    bn_relu_ps_k<<<EW, 256>>>(buf0, up_g, up_be, buf1);   // buf1 = dep

    // attention-map path
    up_sig_k<<<1024, 256>>>(in_map);
    inc_k<<<1024, 256>>>();
    mult_k<<<EW, 256>>>(cur_x);                            // buf2 = b_feature

    // conv2 (tensor) + fused (dep + beta*fn): buf0 = buf1 + beta*(conv(buf2)+b)
    tconv3x3<false, true><<<gT, 256, T_SMEM>>>(buf2, conv2_w, conv2_b, buf0,
                                               nullptr, nullptr, buf1, beta);
    // d1 (tensor): conv(raw) -> buf2 ; stats
    tconv3x3<false, false><<<gT, 256, T_SMEM>>>(buf0, d1_w, d1_b, buf2,
                                                nullptr, nullptr, nullptr, nullptr);
    bn_stats_k<<<64, 256>>>(buf2, 64, 16384, 16);
    // d2 (tensor, fused BN1+ReLU on input) -> buf1 ; stats
    tconv3x3<true, false><<<gT, 256, T_SMEM>>>(buf2, d2_w, d2_b, buf1,
                                               d1_g, d1_be, nullptr, nullptr);
    bn_stats_k<<<64, 256>>>(buf1, 64, 16384, 16);
    // d3 (tensor, fused BN2+ReLU on input) -> buf2 ; stats
    tconv3x3<true, false><<<gT, 256, T_SMEM>>>(buf1, d3_w, d3_b, buf2,
                                               d2_g, d2_be, nullptr, nullptr);
    bn_stats_k<<<64, 256>>>(buf2, 64, 16384, 16);
    // r = BN3 + ReLU -> output region
    bn_relu_out_k<<<EW, 256>>>(buf2, d3_g, d3_be, r_out);

    // output_map = conv7x7(r)
    conv7x7_k<<<dim3(8, 8, 16), dim3(16, 16)>>>(r_out, out_w, out_b, map_out);
}

// round 14
// speedup vs baseline: 2.9001x; 1.7412x over previous
#include <cuda_runtime.h>
#include <cuda_bf16.h>
#include <math.h>

// ---------------- scratch (no allocation allowed) ----------------
#define NEL 16777216  // 16*64*128*128  == 16*256*64*64
__device__ float g_buf0[NEL];
__device__ float g_buf1[NEL];
__device__ float g_buf2[NEL];
__device__ float g_imap[262144];   // 16*128*128
__device__ float g_inc[262144];
__device__ float g_mean[256];
__device__ float g_rstd[256];
__device__ float g_part[4096];     // 256*16
__device__ float g_part2[4096];
// pre-split weights: up(294912) + conv2,d1,d2,d3 (36864 each)
__device__ __nv_bfloat16 g_wh[442368];
__device__ __nv_bfloat16 g_wl[442368];
#define WOFS_UP 0
#define WOFS_C2 294912
#define WOFS_D1 331776
#define WOFS_D2 368640
#define WOFS_D3 405504

typedef unsigned int u32;

// ---------------- weight prep: fp32 [co][ci][3][3] -> bf16 hi/lo [dy][dx][co][ci] ----
__global__ void wprep_k(const float* __restrict__ wt, __nv_bfloat16* __restrict__ bh,
                        __nv_bfloat16* __restrict__ bl, int Cout, int Cin) {
    int idx = blockIdx.x * 256 + threadIdx.x;
    if (idx >= Cout * Cin * 9) return;
    int dx = idx % 3; int r = idx / 3; int dy = r % 3; r /= 3;
    int ci = r % Cin; int co = r / Cin;
    float w = wt[idx];
    __nv_bfloat16 h = __float2bfloat16_rn(w);
    int o = ((dy * 3 + dx) * Cout + co) * Cin + ci;
    bh[o] = h;
    bl[o] = __float2bfloat16_rn(w - __bfloat162float(h));
}

__device__ __forceinline__ void mma16816(float* d, const u32* a, const u32* b) {
    asm volatile(
        "mma.sync.aligned.m16n8k16.row.col.f32.bf16.bf16.f32 "
        "{%0,%1,%2,%3}, {%4,%5,%6,%7}, {%8,%9}, {%0,%1,%2,%3};"
        : "+f"(d[0]), "+f"(d[1]), "+f"(d[2]), "+f"(d[3])
        : "r"(a[0]), "r"(a[1]), "r"(a[2]), "r"(a[3]), "r"(b[0]), "r"(b[1]));
}

// ================= d-conv: mma.sync 3x3, 64->64, H=W=128 =================
#define A_HI 0
#define A_LO 18944
#define B_HI 37888
#define B_LO 65536
#define T_SMEM 93184
#define AST 72
#define EPST 68

template<bool BNIN, bool ADDDEP>
__global__ void __launch_bounds__(256, 2)
tconv3x3(const float* __restrict__ in, const __nv_bfloat16* __restrict__ wh,
         const __nv_bfloat16* __restrict__ wl,
         const float* __restrict__ bias_, float* __restrict__ out,
         const float* __restrict__ bng, const float* __restrict__ bnbe,
         const float* __restrict__ addsrc, const float* __restrict__ betap) {
    extern __shared__ char smem[];
    __nv_bfloat16* Ah = (__nv_bfloat16*)(smem + A_HI);
    __nv_bfloat16* Al = (__nv_bfloat16*)(smem + A_LO);
    __nv_bfloat16* Bh = (__nv_bfloat16*)(smem + B_HI);
    __nv_bfloat16* Bl = (__nv_bfloat16*)(smem + B_LO);
    const int tid = threadIdx.x;
    const int w = tid >> 5, lane = tid & 31;
    const int wm = w & 3, wn = w >> 2;
    const int g = lane >> 2, t = lane & 3;
    const int y = blockIdx.x, n = blockIdx.y;

    if (tid < 128) {
        int b = tid >> 6, r = (tid >> 5) & 1, wd = tid & 31;
        __nv_bfloat16* dst = b ? Al : Ah;
        *(u32*)&dst[(r ? 129 : 0) * AST + wd * 2] = 0u;
    }

    float acc[2][4][4];
    #pragma unroll
    for (int mi = 0; mi < 2; mi++)
        #pragma unroll
        for (int ni = 0; ni < 4; ni++)
            #pragma unroll
            for (int j = 0; j < 4; j++) acc[mi][ni][j] = 0.f;

    #pragma unroll
    for (int dy = 0; dy < 3; dy++) {
        const int u = y + dy - 1;
        if (u < 0 || u > 127) continue;
        __syncthreads();

        const float* ip = in + (((size_t)n * 64) * 128 + u) * 128;
        for (int it = tid; it < 8192; it += 256) {
            int ci = it >> 7, xx = it & 127;
            float v = ip[(size_t)ci * 16384 + xx];
            if (BNIN) {
                float s = g_rstd[ci] * bng[ci];
                v = fmaxf(fmaf(v, s, bnbe[ci] - g_mean[ci] * s), 0.f);
            }
            __nv_bfloat16 hb = __float2bfloat16_rn(v);
            float h = __bfloat162float(hb);
            Ah[(xx + 1) * AST + ci] = hb;
            Al[(xx + 1) * AST + ci] = __float2bfloat16_rn(v - h);
        }
        // B from pre-split weights: rows (dx*64+co) x 32 u32, coalesced
        {
            const u32* wbh = (const u32*)wh + dy * 6144;
            const u32* wbl = (const u32*)wl + dy * 6144;
            for (int it = tid; it < 6144; it += 256) {
                int row = it >> 5, j = it & 31;
                *(u32*)&Bh[row * AST + j * 2] = wbh[it];
                *(u32*)&Bl[row * AST + j * 2] = wbl[it];
            }
        }
        __syncthreads();

        #pragma unroll
        for (int dx = 0; dx < 3; dx++) {
            const int ar0 = dx + wm * 32 + g;
            const int bn0 = dx * 64 + wn * 32 + g;
            #pragma unroll
            for (int ks = 0; ks < 4; ks++) {
                const int k0 = ks * 16 + t * 2;
                u32 ah[2][4], al[2][4];
                #pragma unroll
                for (int mi = 0; mi < 2; mi++) {
                    int r0 = ar0 + mi * 16;
                    ah[mi][0] = *(const u32*)&Ah[r0 * AST + k0];
                    ah[mi][1] = *(const u32*)&Ah[(r0 + 8) * AST + k0];
                    ah[mi][2] = *(const u32*)&Ah[r0 * AST + k0 + 8];
                    ah[mi][3] = *(const u32*)&Ah[(r0 + 8) * AST + k0 + 8];
                    al[mi][0] = *(const u32*)&Al[r0 * AST + k0];
                    al[mi][1] = *(const u32*)&Al[(r0 + 8) * AST + k0];
                    al[mi][2] = *(const u32*)&Al[r0 * AST + k0 + 8];
                    al[mi][3] = *(const u32*)&Al[(r0 + 8) * AST + k0 + 8];
                }
                u32 bh[4][2], bl[4][2];
                #pragma unroll
                for (int ni = 0; ni < 4; ni++) {
                    int br = bn0 + ni * 8;
                    bh[ni][0] = *(const u32*)&Bh[br * AST + k0];
                    bh[ni][1] = *(const u32*)&Bh[br * AST + k0 + 8];
                    bl[ni][0] = *(const u32*)&Bl[br * AST + k0];
                    bl[ni][1] = *(const u32*)&Bl[br * AST + k0 + 8];
                }
                #pragma unroll
                for (int mi = 0; mi < 2; mi++)
                    #pragma unroll
                    for (int ni = 0; ni < 4; ni++) {
                        mma16816(acc[mi][ni], ah[mi], bh[ni]);
                        mma16816(acc[mi][ni], ah[mi], bl[ni]);
                        mma16816(acc[mi][ni], al[mi], bh[ni]);
                    }
            }
        }
    }

    __syncthreads();
    float* ep = (float*)smem;
    #pragma unroll
    for (int mi = 0; mi < 2; mi++)
        #pragma unroll
        for (int ni = 0; ni < 4; ni++) {
            int x = wm * 32 + mi * 16 + g;
            int co = wn * 32 + ni * 8 + 2 * t;
            ep[x * EPST + co]           = acc[mi][ni][0];
            ep[x * EPST + co + 1]       = acc[mi][ni][1];
            ep[(x + 8) * EPST + co]     = acc[mi][ni][2];
            ep[(x + 8) * EPST + co + 1] = acc[mi][ni][3];
        }
    __syncthreads();
    const float beta = ADDDEP ? betap[0] : 0.f;
    for (int it = tid; it < 8192; it += 256) {
        int co = it >> 7, x = it & 127;
        float v = ep[x * EPST + co] + bias_[co];
        size_t o = (((size_t)n * 64 + co) * 128 + y) * 128 + x;
        if (ADDDEP) v = fmaf(beta, v, addsrc[o]);
        out[o] = v;
    }
}

// ================= up-conv: mma.sync 3x3, 128->256, H=W=64 =================
// CTA = one output row y, batch n, co-block 32 (cog 0..7). M=64 px, K=128 ci.
#define UA_HI 0
#define UA_LO 17984
#define UB_HI 35968
#define UB_LO 62080
#define U_SMEM 88192
#define UAST 136

__global__ void __launch_bounds__(256, 2)
uconv3x3(const float* __restrict__ in, const float* __restrict__ bias_,
         float* __restrict__ out) {
    extern __shared__ char smem[];
    __nv_bfloat16* Ah = (__nv_bfloat16*)(smem + UA_HI);
    __nv_bfloat16* Al = (__nv_bfloat16*)(smem + UA_LO);
    __nv_bfloat16* Bh = (__nv_bfloat16*)(smem + UB_HI);
    __nv_bfloat16* Bl = (__nv_bfloat16*)(smem + UB_LO);
    const int tid = threadIdx.x;
    const int w = tid >> 5, lane = tid & 31;
    const int wm = w & 1, wn = w >> 1;       // M 2x32, N 4x8
    const int g = lane >> 2, t = lane & 3;
    const int y = blockIdx.x, n = blockIdx.y, cog = blockIdx.z;

    // zero A pad rows 0 and 65 (hi+lo)
    if (tid < 256) {
        int p = tid >> 7, r = (tid >> 6) & 1, j = tid & 63;
        __nv_bfloat16* dst = p ? Al : Ah;
        *(u32*)&dst[(r ? 65 : 0) * UAST + j * 2] = 0u;
    }

    float acc[2][4];
    #pragma unroll
    for (int mi = 0; mi < 2; mi++)
        #pragma unroll
        for (int j = 0; j < 4; j++) acc[mi][j] = 0.f;

    #pragma unroll
    for (int dy = 0; dy < 3; dy++) {
        const int u = y + dy - 1;
        if (u < 0 || u > 63) continue;
        __syncthreads();

        // A: input row u, 128 ci x 64 x
        const float* ip = in + (((size_t)n * 128) * 64 + u) * 64;
        for (int it = tid; it < 8192; it += 256) {
            int ci = it >> 6, xx = it & 63;
            float v = ip[(size_t)ci * 4096 + xx];
            __nv_bfloat16 hb = __float2bfloat16_rn(v);
            float h = __bfloat162float(hb);
            Ah[(xx + 1) * UAST + ci] = hb;
            Al[(xx + 1) * UAST + ci] = __float2bfloat16_rn(v - h);
        }
        // B: rows dx*32+co (96), 64 u32 each, from pre-split up weights
        {
            const u32* wbh = (const u32*)(g_wh + WOFS_UP);
            const u32* wbl = (const u32*)(g_wl + WOFS_UP);
            for (int it = tid; it < 6144; it += 256) {
                int row = it >> 6, j = it & 63;
                int dx = row >> 5, co = row & 31;
                int grow = dy * 768 + dx * 256 + cog * 32 + co;
                *(u32*)&Bh[row * UAST + j * 2] = wbh[grow * 64 + j];
                *(u32*)&Bl[row * UAST + j * 2] = wbl[grow * 64 + j];
            }
        }
        __syncthreads();

        #pragma unroll
        for (int dx = 0; dx < 3; dx++) {
            const int ar0 = wm * 32 + g + dx;
            const int br = dx * 32 + wn * 8 + g;
            #pragma unroll
            for (int ks = 0; ks < 8; ks++) {
                const int k0 = ks * 16 + t * 2;
                u32 ah[2][4], al[2][4];
                #pragma unroll
                for (int mi = 0; mi < 2; mi++) {
                    int r0 = ar0 + mi * 16;
                    ah[mi][0] = *(const u32*)&Ah[r0 * UAST + k0];
                    ah[mi][1] = *(const u32*)&Ah[(r0 + 8) * UAST + k0];
                    ah[mi][2] = *(const u32*)&Ah[r0 * UAST + k0 + 8];
                    ah[mi][3] = *(const u32*)&Ah[(r0 + 8) * UAST + k0 + 8];
                    al[mi][0] = *(const u32*)&Al[r0 * UAST + k0];
                    al[mi][1] = *(const u32*)&Al[(r0 + 8) * UAST + k0];
                    al[mi][2] = *(const u32*)&Al[r0 * UAST + k0 + 8];
                    al[mi][3] = *(const u32*)&Al[(r0 + 8) * UAST + k0 + 8];
                }
                u32 bh[2], bl[2];
                bh[0] = *(const u32*)&Bh[br * UAST + k0];
                bh[1] = *(const u32*)&Bh[br * UAST + k0 + 8];
                bl[0] = *(const u32*)&Bl[br * UAST + k0];
                bl[1] = *(const u32*)&Bl[br * UAST + k0 + 8];
                #pragma unroll
                for (int mi = 0; mi < 2; mi++) {
                    mma16816(acc[mi], ah[mi], bh);
                    mma16816(acc[mi], ah[mi], bl);
                    mma16816(acc[mi], al[mi], bh);
                }
            }
        }
    }

    __syncthreads();
    float* ep = (float*)smem;
    #pragma unroll
    for (int mi = 0; mi < 2; mi++) {
        int x = wm * 32 + mi * 16 + g;
        int co = wn * 8 + 2 * t;
        ep[x * EPST + co]           = acc[mi][0];
        ep[x * EPST + co + 1]       = acc[mi][1];
        ep[(x + 8) * EPST + co]     = acc[mi][2];
        ep[(x + 8) * EPST + co + 1] = acc[mi][3];
    }
    __syncthreads();
    for (int it = tid; it < 2048; it += 256) {
        int co = it >> 6, x = it & 63;
        float v = ep[x * EPST + co] + bias_[cog * 32 + co];
        out[(((size_t)n * 256 + cog * 32 + co) * 64 + y) * 64 + x] = v;
    }
}

// ---------------- BN stats: two-stage deterministic ----------------
__global__ void bn_part_k(const float* __restrict__ x, int C, int HW) {
    const int c = blockIdx.x, b = blockIdx.y;
    const float* p = x + ((size_t)b * C + c) * HW;
    float s = 0.f, s2 = 0.f;
    for (int i = threadIdx.x; i < HW; i += 256) { float v = p[i]; s += v; s2 += v * v; }
    __shared__ float sh[256], sh2[256];
    sh[threadIdx.x] = s; sh2[threadIdx.x] = s2;
    __syncthreads();
    for (int o = 128; o > 0; o >>= 1) {
        if (threadIdx.x < o) { sh[threadIdx.x] += sh[threadIdx.x + o]; sh2[threadIdx.x] += sh2[threadIdx.x + o]; }
        __syncthreads();
    }
    if (threadIdx.x == 0) { g_part[c * 16 + b] = sh[0]; g_part2[c * 16 + b] = sh2[0]; }
}
__global__ void bn_fin_k(int C, float invN) {
    int c = blockIdx.x * 64 + threadIdx.x;
    if (c >= C) return;
    float s = 0.f, s2 = 0.f;
    #pragma unroll
    for (int b = 0; b < 16; b++) { s += g_part[c * 16 + b]; s2 += g_part2[c * 16 + b]; }
    float m = s * invN;
    g_mean[c] = m;
    g_rstd[c] = rsqrtf(s2 * invN - m * m + 1e-5f);
}

// ---------------- BN apply + ReLU + PixelShuffle(2) ----------------
__global__ void bn_relu_ps_k(const float* __restrict__ y, const float* __restrict__ g,
                             const float* __restrict__ be, float* __restrict__ dep) {
    int idx = blockIdx.x * 256 + threadIdx.x;
    int X = idx & 127;
    int Y = (idx >> 7) & 127;
    int c = (idx >> 14) & 63;
    int n = idx >> 20;
    int cy = c * 4 + (Y & 1) * 2 + (X & 1);
    float v = y[(((size_t)n * 256 + cy) * 64 + (Y >> 1)) * 64 + (X >> 1)];
    v = (v - g_mean[cy]) * g_rstd[cy] * g[cy] + be[cy];
    dep[idx] = fmaxf(v, 0.f);
}

__global__ void bn_relu_out_k(const float* __restrict__ x, const float* __restrict__ g,
                              const float* __restrict__ be, float* __restrict__ dst) {
    int idx = blockIdx.x * 256 + threadIdx.x;
    int c = (idx >> 14) & 63;
    float v = x[idx];
    v = (v - g_mean[c]) * g_rstd[c] * g[c] + be[c];
    dst[idx] = fmaxf(v, 0.f);
}

__global__ void up_sig_k(const float* __restrict__ in) {
    int idx = blockIdx.x * 256 + threadIdx.x;
    int X = idx & 127, Y = (idx >> 7) & 127, n = idx >> 14;
    const float sc = 63.0f / 127.0f;
    float yy = Y * sc, xx = X * sc;
    int y0 = (int)floorf(yy); float wy = yy - (float)y0; int y1 = min(y0 + 1, 63);
    int x0 = (int)floorf(xx); float wx = xx - (float)x0; int x1 = min(x0 + 1, 63);
    const float* p = in + n * 4096;
    float r0 = p[y0 * 64 + x0] * (1.f - wx) + p[y0 * 64 + x1] * wx;
    float r1 = p[y1 * 64 + x0] * (1.f - wx) + p[y1 * 64 + x1] * wx;
    float v = r0 * (1.f - wy) + r1 * wy;
    g_imap[idx] = 1.f / (1.f + expf(-v));
}

__global__ void inc_k() {
    int idx = blockIdx.x * 256 + threadIdx.x;
    int X = idx & 127, Y = (idx >> 7) & 127, n = idx >> 14;
    const float* p = g_imap + (n << 14);
    float m = -1e30f;
    #pragma unroll
    for (int dy = -1; dy <= 1; dy++) {
        int y = Y + dy;
        if (y < 0 || y > 127) continue;
        #pragma unroll
        for (int dx = -1; dx <= 1; dx++) {
            int x = X + dx;
            if (x < 0 || x > 127) continue;
            m = fmaxf(m, p[y * 128 + x]);
        }
    }
    g_inc[idx] = m - p[Y * 128 + X];
}

__global__ void mult_k(const float* __restrict__ cur) {
    int idx = blockIdx.x * 256 + threadIdx.x;
    int sp = idx & 16383;
    int n = idx >> 20;
    g_buf2[idx] = cur[idx] * g_inc[(n << 14) | sp];
}

__global__ void conv7x7_k(const float* __restrict__ in, const float* __restrict__ wt,
                          const float* __restrict__ bias, float* __restrict__ out) {
    __shared__ float tile[22][22];
    __shared__ float wsm[64 * 49];
    const int n = blockIdx.z;
    const int tid = threadIdx.y * 16 + threadIdx.x;
    for (int i = tid; i < 64 * 49; i += 256) wsm[i] = wt[i];
    const int oy0 = blockIdx.y * 16, ox0 = blockIdx.x * 16;
    float acc = 0.f;
    for (int ci = 0; ci < 64; ci++) {
        __syncthreads();
        const float* ip = in + ((size_t)n * 64 + ci) * 16384;
        for (int i = tid; i < 22 * 22; i += 256) {
            int ly = i / 22, lx = i % 22;
            int gy = oy0 + ly - 3, gx = ox0 + lx - 3;
            float v = 0.f;
            if (gy >= 0 && gy < 128 && gx >= 0 && gx < 128) v = ip[gy * 128 + gx];
            tile[ly][lx] = v;
        }
        __syncthreads();
        const float* wp = &wsm[ci * 49];
        #pragma unroll
        for (int dy = 0; dy < 7; dy++)
            #pragma unroll
            for (int dx = 0; dx < 7; dx++)
                acc = fmaf(tile[threadIdx.y + dy][threadIdx.x + dx], wp[dy * 7 + dx], acc);
    }
    out[((size_t)n * 128 + oy0 + threadIdx.y) * 128 + ox0 + threadIdx.x] = acc + bias[0];
}

// ---------------- launch ----------------
extern "C" void kernel_launch(void* const* d_in, const int* in_sizes, int n_in,
                              void* d_out, int out_size) {
    static float *buf0 = nullptr, *buf1 = nullptr, *buf2 = nullptr;
    static __nv_bfloat16 *wh = nullptr, *wl = nullptr;
    if (!buf0) {
        cudaGetSymbolAddress((void**)&buf0, g_buf0);
        cudaGetSymbolAddress((void**)&buf1, g_buf1);
        cudaGetSymbolAddress((void**)&buf2, g_buf2);
        cudaGetSymbolAddress((void**)&wh, g_wh);
        cudaGetSymbolAddress((void**)&wl, g_wl);
        cudaFuncSetAttribute(tconv3x3<false, true>,  cudaFuncAttributeMaxDynamicSharedMemorySize, T_SMEM);
        cudaFuncSetAttribute(tconv3x3<false, false>, cudaFuncAttributeMaxDynamicSharedMemorySize, T_SMEM);
        cudaFuncSetAttribute(tconv3x3<true,  false>, cudaFuncAttributeMaxDynamicSharedMemorySize, T_SMEM);
        cudaFuncSetAttribute(uconv3x3, cudaFuncAttributeMaxDynamicSharedMemorySize, U_SMEM);
    }
    const float* cur_x  = (const float*)d_in[0];
    const float* dep_x  = (const float*)d_in[1];
    const float* in_map = (const float*)d_in[2];
    const float* up_w   = (const float*)d_in[3];
    const float* up_b   = (const float*)d_in[4];
    const float* up_g   = (const float*)d_in[5];
    const float* up_be  = (const float*)d_in[6];
    const float* conv2_w = (const float*)d_in[7];
    const float* conv2_b = (const float*)d_in[8];
    const float* beta   = (const float*)d_in[9];
    const float* d1_w = (const float*)d_in[10], *d1_b = (const float*)d_in[11];
    const float* d1_g = (const float*)d_in[12], *d1_be = (const float*)d_in[13];
    const float* d2_w = (const float*)d_in[14], *d2_b = (const float*)d_in[15];
    const float* d2_g = (const float*)d_in[16], *d2_be = (const float*)d_in[17];
    const float* d3_w = (const float*)d_in[18], *d3_b = (const float*)d_in[19];
    const float* d3_g = (const float*)d_in[20], *d3_be = (const float*)d_in[21];
    const float* out_w = (const float*)d_in[22], *out_b = (const float*)d_in[23];

    float* r_out = (float*)d_out;               // [16,64,128,128]
    float* map_out = (float*)d_out + NEL;       // [16,1,128,128]

    const int EW = NEL / 256;

    // weight prep (once per launch, graph-capturable)
    wprep_k<<<1152, 256>>>(up_w,    wh + WOFS_UP, wl + WOFS_UP, 256, 128);
    wprep_k<<<144,  256>>>(conv2_w, wh + WOFS_C2, wl + WOFS_C2, 64, 64);
    wprep_k<<<144,  256>>>(d1_w,    wh + WOFS_D1, wl + WOFS_D1, 64, 64);
    wprep_k<<<144,  256>>>(d2_w,    wh + WOFS_D2, wl + WOFS_D2, 64, 64);
    wprep_k<<<144,  256>>>(d3_w,    wh + WOFS_D3, wl + WOFS_D3, 64, 64);

    // up path: conv(C2->4C1) via mma + BN + ReLU + pixel shuffle
    uconv3x3<<<dim3(64, 16, 8), 256, U_SMEM>>>(dep_x, up_b, buf0);
    bn_part_k<<<dim3(256, 16), 256>>>(buf0, 256, 4096);
    bn_fin_k<<<4, 64>>>(256, 1.f / 65536.f);
    bn_relu_ps_k<<<EW, 256>>>(buf0, up_g, up_be, buf1);   // buf1 = dep

    // attention-map path
    up_sig_k<<<1024, 256>>>(in_map);
    inc_k<<<1024, 256>>>();
    mult_k<<<EW, 256>>>(cur_x);                            // buf2 = b_feature

    dim3 gT(128, 16);
    // conv2 + fused (dep + beta*fn)
    tconv3x3<false, true><<<gT, 256, T_SMEM>>>(buf2, wh + WOFS_C2, wl + WOFS_C2,
                                               conv2_b, buf0, nullptr, nullptr, buf1, beta);
    // d1
    tconv3x3<false, false><<<gT, 256, T_SMEM>>>(buf0, wh + WOFS_D1, wl + WOFS_D1,
                                                d1_b, buf2, nullptr, nullptr, nullptr, nullptr);
    bn_part_k<<<dim3(64, 16), 256>>>(buf2, 64, 16384);
    bn_fin_k<<<1, 64>>>(64, 1.f / 262144.f);
    // d2 (fused BN1+ReLU on input)
    tconv3x3<true, false><<<gT, 256, T_SMEM>>>(buf2, wh + WOFS_D2, wl + WOFS_D2,
                                               d2_b, buf1, d1_g, d1_be, nullptr, nullptr);
    bn_part_k<<<dim3(64, 16), 256>>>(buf1, 64, 16384);
    bn_fin_k<<<1, 64>>>(64, 1.f / 262144.f);
    // d3 (fused BN2+ReLU on input)
    tconv3x3<true, false><<<gT, 256, T_SMEM>>>(buf1, wh + WOFS_D3, wl + WOFS_D3,
                                               d3_b, buf2, d2_g, d2_be, nullptr, nullptr);
    bn_part_k<<<dim3(64, 16), 256>>>(buf2, 64, 16384);
    bn_fin_k<<<1, 64>>>(64, 1.f / 262144.f);
    // r = BN3 + ReLU -> output region
    bn_relu_out_k<<<EW, 256>>>(buf2, d3_g, d3_be, r_out);

    // output_map = conv7x7(r)
    conv7x7_k<<<dim3(8, 8, 16), dim3(16, 16)>>>(r_out, out_w, out_b, map_out);
}

// round 16
// speedup vs baseline: 3.1364x; 1.0815x over previous
#include <cuda_runtime.h>
#include <cuda_bf16.h>
#include <math.h>

// ---------------- scratch (no allocation allowed) ----------------
#define NEL 16777216  // 16*64*128*128  == 16*256*64*64
__device__ float g_buf0[NEL];
__device__ float g_buf1[NEL];
__device__ float g_buf2[NEL];
__device__ float g_imap[262144];   // 16*128*128
__device__ float g_inc[262144];
__device__ float g_mean[256];
__device__ float g_rstd[256];
__device__ float g_part[4096];     // 256*16
__device__ float g_part2[4096];
// pre-split weights: up(294912) + conv2,d1,d2,d3 (36864 each)
__device__ __nv_bfloat16 g_wh[442368];
__device__ __nv_bfloat16 g_wl[442368];
// pre-split dep_x, transposed [n][y][x][ci]: 16*64*64*128 = 8388608
__device__ __nv_bfloat16 g_xh[8388608];
__device__ __nv_bfloat16 g_xl[8388608];
#define WOFS_UP 0
#define WOFS_C2 294912
#define WOFS_D1 331776
#define WOFS_D2 368640
#define WOFS_D3 405504

typedef unsigned int u32;

// ---------------- weight prep: fp32 [co][ci][3][3] -> bf16 hi/lo [dy][dx][co][ci] ----
__global__ void wprep_k(const float* __restrict__ wt, __nv_bfloat16* __restrict__ bh,
                        __nv_bfloat16* __restrict__ bl, int Cout, int Cin) {
    int idx = blockIdx.x * 256 + threadIdx.x;
    if (idx >= Cout * Cin * 9) return;
    int dx = idx % 3; int r = idx / 3; int dy = r % 3; r /= 3;
    int ci = r % Cin; int co = r / Cin;
    float w = wt[idx];
    __nv_bfloat16 h = __float2bfloat16_rn(w);
    int o = ((dy * 3 + dx) * Cout + co) * Cin + ci;
    bh[o] = h;
    bl[o] = __float2bfloat16_rn(w - __bfloat162float(h));
}

// ---------------- dep_x pre-split: fp32 [n][ci][y][x] -> bf16 hi/lo [n][y][x][ci] ----
__global__ void xsplit_k(const float* __restrict__ in) {
    __shared__ float tile[32][133];
    const int xb = blockIdx.x, y = blockIdx.y, n = blockIdx.z;
    const int tid = threadIdx.x;
    const int lx = tid & 31, c0 = tid >> 5;
    const int x0 = xb * 32;
    #pragma unroll
    for (int k = 0; k < 16; k++) {
        int ci = c0 + k * 8;
        tile[lx][ci] = in[(((size_t)n * 128 + ci) * 64 + y) * 64 + x0 + lx];
    }
    __syncthreads();
    u32* oh = (u32*)g_xh + (((size_t)n * 64 + y) * 64 + x0) * 64;
    u32* ol = (u32*)g_xl + (((size_t)n * 64 + y) * 64 + x0) * 64;
    for (int it = tid; it < 2048; it += 256) {
        int x = it >> 6, j = it & 63;
        float v0 = tile[x][2 * j], v1 = tile[x][2 * j + 1];
        __nv_bfloat16 h0 = __float2bfloat16_rn(v0), h1 = __float2bfloat16_rn(v1);
        float f0 = __bfloat162float(h0), f1 = __bfloat162float(h1);
        __nv_bfloat16 l0 = __float2bfloat16_rn(v0 - f0), l1 = __float2bfloat16_rn(v1 - f1);
        oh[it] = ((u32)__bfloat16_as_ushort(h1) << 16) | (u32)__bfloat16_as_ushort(h0);
        ol[it] = ((u32)__bfloat16_as_ushort(l1) << 16) | (u32)__bfloat16_as_ushort(l0);
    }
}

__device__ __forceinline__ void mma16816(float* d, const u32* a, const u32* b) {
    asm volatile(
        "mma.sync.aligned.m16n8k16.row.col.f32.bf16.bf16.f32 "
        "{%0,%1,%2,%3}, {%4,%5,%6,%7}, {%8,%9}, {%0,%1,%2,%3};"
        : "+f"(d[0]), "+f"(d[1]), "+f"(d[2]), "+f"(d[3])
        : "r"(a[0]), "r"(a[1]), "r"(a[2]), "r"(a[3]), "r"(b[0]), "r"(b[1]));
}

// ================= d-conv: mma.sync 3x3, 64->64, H=W=128 =================
#define A_HI 0
#define A_LO 18944
#define B_HI 37888
#define B_LO 65536
#define T_SMEM 93184
#define AST 72
#define EPST 68

template<bool BNIN, bool MULIN, int EPI>
__global__ void __launch_bounds__(256, 2)
tconv3x3(const float* __restrict__ in, const __nv_bfloat16* __restrict__ wh,
         const __nv_bfloat16* __restrict__ wl,
         const float* __restrict__ bias_, float* __restrict__ out,
         const float* __restrict__ bng, const float* __restrict__ bnbe,
         const float* __restrict__ addsrc, const float* __restrict__ betap) {
    extern __shared__ char smem[];
    __nv_bfloat16* Ah = (__nv_bfloat16*)(smem + A_HI);
    __nv_bfloat16* Al = (__nv_bfloat16*)(smem + A_LO);
    __nv_bfloat16* Bh = (__nv_bfloat16*)(smem + B_HI);
    __nv_bfloat16* Bl = (__nv_bfloat16*)(smem + B_LO);
    const int tid = threadIdx.x;
    const int w = tid >> 5, lane = tid & 31;
    const int wm = w & 3, wn = w >> 2;
    const int g = lane >> 2, t = lane & 3;
    const int y = blockIdx.x, n = blockIdx.y;

    if (tid < 128) {
        int b = tid >> 6, r = (tid >> 5) & 1, wd = tid & 31;
        __nv_bfloat16* dst = b ? Al : Ah;
        *(u32*)&dst[(r ? 129 : 0) * AST + wd * 2] = 0u;
    }

    float acc[2][4][4];
    #pragma unroll
    for (int mi = 0; mi < 2; mi++)
        #pragma unroll
        for (int ni = 0; ni < 4; ni++)
            #pragma unroll
            for (int j = 0; j < 4; j++) acc[mi][ni][j] = 0.f;

    #pragma unroll
    for (int dy = 0; dy < 3; dy++) {
        const int u = y + dy - 1;
        if (u < 0 || u > 127) continue;
        __syncthreads();

        const float* ip = in + (((size_t)n * 64) * 128 + u) * 128;
        const float* incp = MULIN ? (g_inc + ((size_t)n << 14) + u * 128) : (const float*)0;
        for (int it = tid; it < 8192; it += 256) {
            int ci = it >> 7, xx = it & 127;
            float v = ip[(size_t)ci * 16384 + xx];
            if (MULIN) v *= incp[xx];
            if (BNIN) {
                float s = g_rstd[ci] * bng[ci];
                v = fmaxf(fmaf(v, s, bnbe[ci] - g_mean[ci] * s), 0.f);
            }
            __nv_bfloat16 hb = __float2bfloat16_rn(v);
            float h = __bfloat162float(hb);
            Ah[(xx + 1) * AST + ci] = hb;
            Al[(xx + 1) * AST + ci] = __float2bfloat16_rn(v - h);
        }
        {
            const u32* wbh = (const u32*)wh + dy * 6144;
            const u32* wbl = (const u32*)wl + dy * 6144;
            for (int it = tid; it < 6144; it += 256) {
                int row = it >> 5, j = it & 31;
                *(u32*)&Bh[row * AST + j * 2] = wbh[it];
                *(u32*)&Bl[row * AST + j * 2] = wbl[it];
            }
        }
        __syncthreads();

        #pragma unroll
        for (int dx = 0; dx < 3; dx++) {
            const int ar0 = dx + wm * 32 + g;
            const int bn0 = dx * 64 + wn * 32 + g;
            #pragma unroll
            for (int ks = 0; ks < 4; ks++) {
                const int k0 = ks * 16 + t * 2;
                u32 ah[2][4], al[2][4];
                #pragma unroll
                for (int mi = 0; mi < 2; mi++) {
                    int r0 = ar0 + mi * 16;
                    ah[mi][0] = *(const u32*)&Ah[r0 * AST + k0];
                    ah[mi][1] = *(const u32*)&Ah[(r0 + 8) * AST + k0];
                    ah[mi][2] = *(const u32*)&Ah[r0 * AST + k0 + 8];
                    ah[mi][3] = *(const u32*)&Ah[(r0 + 8) * AST + k0 + 8];
                    al[mi][0] = *(const u32*)&Al[r0 * AST + k0];
                    al[mi][1] = *(const u32*)&Al[(r0 + 8) * AST + k0];
                    al[mi][2] = *(const u32*)&Al[r0 * AST + k0 + 8];
                    al[mi][3] = *(const u32*)&Al[(r0 + 8) * AST + k0 + 8];
                }
                u32 bh[4][2], bl[4][2];
                #pragma unroll
                for (int ni = 0; ni < 4; ni++) {
                    int br = bn0 + ni * 8;
                    bh[ni][0] = *(const u32*)&Bh[br * AST + k0];
                    bh[ni][1] = *(const u32*)&Bh[br * AST + k0 + 8];
                    bl[ni][0] = *(const u32*)&Bl[br * AST + k0];
                    bl[ni][1] = *(const u32*)&Bl[br * AST + k0 + 8];
                }
                #pragma unroll
                for (int mi = 0; mi < 2; mi++)
                    #pragma unroll
                    for (int ni = 0; ni < 4; ni++) {
                        mma16816(acc[mi][ni], ah[mi], bh[ni]);
                        mma16816(acc[mi][ni], ah[mi], bl[ni]);
                        mma16816(acc[mi][ni], al[mi], bh[ni]);
                    }
            }
        }
    }

    __syncthreads();
    float* ep = (float*)smem;
    #pragma unroll
    for (int mi = 0; mi < 2; mi++)
        #pragma unroll
        for (int ni = 0; ni < 4; ni++) {
            int x = wm * 32 + mi * 16 + g;
            int co = wn * 32 + ni * 8 + 2 * t;
            ep[x * EPST + co]           = acc[mi][ni][0];
            ep[x * EPST + co + 1]       = acc[mi][ni][1];
            ep[(x + 8) * EPST + co]     = acc[mi][ni][2];
            ep[(x + 8) * EPST + co + 1] = acc[mi][ni][3];
        }
    __syncthreads();
    const float beta = (EPI == 2) ? betap[0] : 0.f;
    for (int it = tid; it < 8192; it += 256) {
        int co = it >> 7, x = it & 127;
        float v = ep[x * EPST + co] + bias_[co];
        size_t o = (((size_t)n * 64 + co) * 128 + y) * 128 + x;
        if (EPI == 2) {
            int cy = co * 4 + (y & 1) * 2 + (x & 1);
            float dv = addsrc[(((size_t)n * 256 + cy) * 64 + (y >> 1)) * 64 + (x >> 1)];
            dv = fmaxf((dv - g_mean[cy]) * g_rstd[cy] * bng[cy] + bnbe[cy], 0.f);
            v = fmaf(beta, v, dv);
        }
        out[o] = v;
    }
}

// ================= up-conv: mma.sync 3x3, 128->256, H=W=64 =================
#define UA_HI 0
#define UA_LO 17984
#define UB_HI 35968
#define UB_LO 62080
#define U_SMEM 88192
#define UAST 136

__global__ void __launch_bounds__(256, 2)
uconv3x3(const float* __restrict__ bias_, float* __restrict__ out) {
    extern __shared__ char smem[];
    __nv_bfloat16* Ah = (__nv_bfloat16*)(smem + UA_HI);
    __nv_bfloat16* Al = (__nv_bfloat16*)(smem + UA_LO);
    __nv_bfloat16* Bh = (__nv_bfloat16*)(smem + UB_HI);
    __nv_bfloat16* Bl = (__nv_bfloat16*)(smem + UB_LO);
    const int tid = threadIdx.x;
    const int w = tid >> 5, lane = tid & 31;
    const int wm = w & 1, wn = w >> 1;
    const int g = lane >> 2, t = lane & 3;
    const int y = blockIdx.x, n = blockIdx.y, cog = blockIdx.z;

    if (tid < 256) {
        int p = tid >> 7, r = (tid >> 6) & 1, j = tid & 63;
        __nv_bfloat16* dst = p ? Al : Ah;
        *(u32*)&dst[(r ? 65 : 0) * UAST + j * 2] = 0u;
    }

    float acc[2][4];
    #pragma unroll
    for (int mi = 0; mi < 2; mi++)
        #pragma unroll
        for (int j = 0; j < 4; j++) acc[mi][j] = 0.f;

    #pragma unroll
    for (int dy = 0; dy < 3; dy++) {
        const int u = y + dy - 1;
        if (u < 0 || u > 63) continue;
        __syncthreads();

        {
            const u32* xsh = (const u32*)g_xh + (((size_t)n * 64 + u) * 64) * 64;
            const u32* xsl = (const u32*)g_xl + (((size_t)n * 64 + u) * 64) * 64;
            for (int it = tid; it < 4096; it += 256) {
                int xx = it >> 6, j = it & 63;
                *(u32*)&Ah[(xx + 1) * UAST + 2 * j] = xsh[it];
                *(u32*)&Al[(xx + 1) * UAST + 2 * j] = xsl[it];
            }
        }
        {
            const u32* wbh = (const u32*)(g_wh + WOFS_UP);
            const u32* wbl = (const u32*)(g_wl + WOFS_UP);
            for (int it = tid; it < 6144; it += 256) {
                int row = it >> 6, j = it & 63;
                int dx = row >> 5, co = row & 31;
                int grow = dy * 768 + dx * 256 + cog * 32 + co;
                *(u32*)&Bh[row * UAST + j * 2] = wbh[grow * 64 + j];
                *(u32*)&Bl[row * UAST + j * 2] = wbl[grow * 64 + j];
            }
        }
        __syncthreads();

        #pragma unroll
        for (int dx = 0; dx < 3; dx++) {
            const int ar0 = wm * 32 + g + dx;
            const int br = dx * 32 + wn * 8 + g;
            #pragma unroll
            for (int ks = 0; ks < 8; ks++) {
                const int k0 = ks * 16 + t * 2;
                u32 ah[2][4], al[2][4];
                #pragma unroll
                for (int mi = 0; mi < 2; mi++) {
                    int r0 = ar0 + mi * 16;
                    ah[mi][0] = *(const u32*)&Ah[r0 * UAST + k0];
                    ah[mi][1] = *(const u32*)&Ah[(r0 + 8) * UAST + k0];
                    ah[mi][2] = *(const u32*)&Ah[r0 * UAST + k0 + 8];
                    ah[mi][3] = *(const u32*)&Ah[(r0 + 8) * UAST + k0 + 8];
                    al[mi][0] = *(const u32*)&Al[r0 * UAST + k0];
                    al[mi][1] = *(const u32*)&Al[(r0 + 8) * UAST + k0];
                    al[mi][2] = *(const u32*)&Al[r0 * UAST + k0 + 8];
                    al[mi][3] = *(const u32*)&Al[(r0 + 8) * UAST + k0 + 8];
                }
                u32 bh[2], bl[2];
                bh[0] = *(const u32*)&Bh[br * UAST + k0];
                bh[1] = *(const u32*)&Bh[br * UAST + k0 + 8];
                bl[0] = *(const u32*)&Bl[br * UAST + k0];
                bl[1] = *(const u32*)&Bl[br * UAST + k0 + 8];
                #pragma unroll
                for (int mi = 0; mi < 2; mi++) {
                    mma16816(acc[mi], ah[mi], bh);
                    mma16816(acc[mi], ah[mi], bl);
                    mma16816(acc[mi], al[mi], bh);
                }
            }
        }
    }

    __syncthreads();
    float* ep = (float*)smem;
    #pragma unroll
    for (int mi = 0; mi < 2; mi++) {
        int x = wm * 32 + mi * 16 + g;
        int co = wn * 8 + 2 * t;
        ep[x * EPST + co]           = acc[mi][0];
        ep[x * EPST + co + 1]       = acc[mi][1];
        ep[(x + 8) * EPST + co]     = acc[mi][2];
        ep[(x + 8) * EPST + co + 1] = acc[mi][3];
    }
    __syncthreads();
    for (int it = tid; it < 2048; it += 256) {
        int co = it >> 6, x = it & 63;
        float v = ep[x * EPST + co] + bias_[cog * 32 + co];
        out[(((size_t)n * 256 + cog * 32 + co) * 64 + y) * 64 + x] = v;
    }
}

// ---------------- BN stats: two-stage deterministic ----------------
__global__ void bn_part_k(const float* __restrict__ x, int C, int HW) {
    const int c = blockIdx.x, b = blockIdx.y;
    const float* p = x + ((size_t)b * C + c) * HW;
    float s = 0.f, s2 = 0.f;
    for (int i = threadIdx.x; i < HW; i += 256) { float v = p[i]; s += v; s2 += v * v; }
    __shared__ float sh[256], sh2[256];
    sh[threadIdx.x] = s; sh2[threadIdx.x] = s2;
    __syncthreads();
    for (int o = 128; o > 0; o >>= 1) {
        if (threadIdx.x < o) { sh[threadIdx.x] += sh[threadIdx.x + o]; sh2[threadIdx.x] += sh2[threadIdx.x + o]; }
        __syncthreads();
    }
    if (threadIdx.x == 0) { g_part[c * 16 + b] = sh[0]; g_part2[c * 16 + b] = sh2[0]; }
}
__global__ void bn_fin_k(int C, float invN) {
    int c = blockIdx.x * 64 + threadIdx.x;
    if (c >= C) return;
    float s = 0.f, s2 = 0.f;
    #pragma unroll
    for (int b = 0; b < 16; b++) { s += g_part[c * 16 + b]; s2 += g_part2[c * 16 + b]; }
    float m = s * invN;
    g_mean[c] = m;
    g_rstd[c] = rsqrtf(s2 * invN - m * m + 1e-5f);
}

__global__ void bn_relu_out_k(const float* __restrict__ x, const float* __restrict__ g,
                              const float* __restrict__ be, float* __restrict__ dst) {
    int idx = blockIdx.x * 256 + threadIdx.x;
    int c = (idx >> 14) & 63;
    float v = x[idx];
    v = (v - g_mean[c]) * g_rstd[c] * g[c] + be[c];
    dst[idx] = fmaxf(v, 0.f);
}

__global__ void up_sig_k(const float* __restrict__ in) {
    int idx = blockIdx.x * 256 + threadIdx.x;
    int X = idx & 127, Y = (idx >> 7) & 127, n = idx >> 14;
    const float sc = 63.0f / 127.0f;
    float yy = Y * sc, xx = X * sc;
    int y0 = (int)floorf(yy); float wy = yy - (float)y0; int y1 = min(y0 + 1, 63);
    int x0 = (int)floorf(xx); float wx = xx - (float)x0; int x1 = min(x0 + 1, 63);
    const float* p = in + n * 4096;
    float r0 = p[y0 * 64 + x0] * (1.f - wx) + p[y0 * 64 + x1] * wx;
    float r1 = p[y1 * 64 + x0] * (1.f - wx) + p[y1 * 64 + x1] * wx;
    float v = r0 * (1.f - wy) + r1 * wy;
    g_imap[idx] = 1.f / (1.f + expf(-v));
}

__global__ void inc_k() {
    int idx = blockIdx.x * 256 + threadIdx.x;
    int X = idx & 127, Y = (idx >> 7) & 127, n = idx >> 14;
    const float* p = g_imap + (n << 14);
    float m = -1e30f;
    #pragma unroll
    for (int dy = -1; dy <= 1; dy++) {
        int y = Y + dy;
        if (y < 0 || y > 127) continue;
        #pragma unroll
        for (int dx = -1; dx <= 1; dx++) {
            int x = X + dx;
            if (x < 0 || x > 127) continue;
            m = fmaxf(m, p[y * 128 + x]);
        }
    }
    g_inc[idx] = m - p[Y * 128 + X];
}

__global__ void conv7x7_k(const float* __restrict__ in, const float* __restrict__ wt,
                          const float* __restrict__ bias, float* __restrict__ out) {
    __shared__ float tile[22][22];
    __shared__ float wsm[64 * 49];
    const int n = blockIdx.z;
    const int tid = threadIdx.y * 16 + threadIdx.x;
    for (int i = tid; i < 64 * 49; i += 256) wsm[i] = wt[i];
    const int oy0 = blockIdx.y * 16, ox0 = blockIdx.x * 16;
    float acc = 0.f;
    for (int ci = 0; ci < 64; ci++) {
        __syncthreads();
        const float* ip = in + ((size_t)n * 64 + ci) * 16384;
        for (int i = tid; i < 22 * 22; i += 256) {
            int ly = i / 22, lx = i % 22;
            int gy = oy0 + ly - 3, gx = ox0 + lx - 3;
            float v = 0.f;
            if (gy >= 0 && gy < 128 && gx >= 0 && gx < 128) v = ip[gy * 128 + gx];
            tile[ly][lx] = v;
        }
        __syncthreads();
        const float* wp = &wsm[ci * 49];
        #pragma unroll
        for (int dy = 0; dy < 7; dy++)
            #pragma unroll
            for (int dx = 0; dx < 7; dx++)
                acc = fmaf(tile[threadIdx.y + dy][threadIdx.x + dx], wp[dy * 7 + dx], acc);
    }
    out[((size_t)n * 128 + oy0 + threadIdx.y) * 128 + ox0 + threadIdx.x] = acc + bias[0];
}

// ---------------- launch ----------------
extern "C" void kernel_launch(void* const* d_in, const int* in_sizes, int n_in,
                              void* d_out, int out_size) {
    static float *buf0 = nullptr, *buf1 = nullptr, *buf2 = nullptr;
    static __nv_bfloat16 *wh = nullptr, *wl = nullptr;
    if (!buf0) {
        cudaGetSymbolAddress((void**)&buf0, g_buf0);
        cudaGetSymbolAddress((void**)&buf1, g_buf1);
        cudaGetSymbolAddress((void**)&buf2, g_buf2);
        cudaGetSymbolAddress((void**)&wh, g_wh);
        cudaGetSymbolAddress((void**)&wl, g_wl);
        cudaFuncSetAttribute(tconv3x3<false, true,  2>, cudaFuncAttributeMaxDynamicSharedMemorySize, T_SMEM);
        cudaFuncSetAttribute(tconv3x3<false, false, 0>, cudaFuncAttributeMaxDynamicSharedMemorySize, T_SMEM);
        cudaFuncSetAttribute(tconv3x3<true,  false, 0>, cudaFuncAttributeMaxDynamicSharedMemorySize, T_SMEM);
        cudaFuncSetAttribute(uconv3x3, cudaFuncAttributeMaxDynamicSharedMemorySize, U_SMEM);
    }
    const float* cur_x  = (const float*)d_in[0];
    const float* dep_x  = (const float*)d_in[1];
    const float* in_map = (const float*)d_in[2];
    const float* up_w   = (const float*)d_in[3];
    const float* up_b   = (const float*)d_in[4];
    const float* up_g   = (const float*)d_in[5];
    const float* up_be  = (const float*)d_in[6];
    const float* conv2_w = (const float*)d_in[7];
    const float* conv2_b = (const float*)d_in[8];
    const float* beta   = (const float*)d_in[9];
    const float* d1_w = (const float*)d_in[10], *d1_b = (const float*)d_in[11];
    const float* d1_g = (const float*)d_in[12], *d1_be = (const float*)d_in[13];
    const float* d2_w = (const float*)d_in[14], *d2_b = (const float*)d_in[15];
    const float* d2_g = (const float*)d_in[16], *d2_be = (const float*)d_in[17];
    const float* d3_w = (const float*)d_in[18], *d3_b = (const float*)d_in[19];
    const float* d3_g = (const float*)d_in[20], *d3_be = (const float*)d_in[21];
    const float* out_w = (const float*)d_in[22], *out_b = (const float*)d_in[23];

    float* r_out = (float*)d_out;               // [16,64,128,128]
    float* map_out = (float*)d_out + NEL;       // [16,1,128,128]

    const int EW = NEL / 256;

    // prep
    wprep_k<<<1152, 256>>>(up_w,    wh + WOFS_UP, wl + WOFS_UP, 256, 128);
    wprep_k<<<144,  256>>>(conv2_w, wh + WOFS_C2, wl + WOFS_C2, 64, 64);
    wprep_k<<<144,  256>>>(d1_w,    wh + WOFS_D1, wl + WOFS_D1, 64, 64);
    wprep_k<<<144,  256>>>(d2_w,    wh + WOFS_D2, wl + WOFS_D2, 64, 64);
    wprep_k<<<144,  256>>>(d3_w,    wh + WOFS_D3, wl + WOFS_D3, 64, 64);
    xsplit_k<<<dim3(2, 64, 16), 256>>>(dep_x);

    // up path: conv(C2->4C1) -> buf0 (raw); BN stats
    uconv3x3<<<dim3(64, 16, 8), 256, U_SMEM>>>(up_b, buf0);
    bn_part_k<<<dim3(256, 16), 256>>>(buf0, 256, 4096);
    bn_fin_k<<<4, 64>>>(256, 1.f / 65536.f);

    // attention-map path
    up_sig_k<<<1024, 256>>>(in_map);
    inc_k<<<1024, 256>>>();

    dim3 gT(128, 16);
    // conv2: input = cur_x * inc; epilogue = dep(PS+BN+ReLU of buf0) + beta*(conv+b)
    tconv3x3<false, true, 2><<<gT, 256, T_SMEM>>>(cur_x, wh + WOFS_C2, wl + WOFS_C2,
                                                  conv2_b, buf2, up_g, up_be, buf0, beta);
    // d1
    tconv3x3<false, false, 0><<<gT, 256, T_SMEM>>>(buf2, wh + WOFS_D1, wl + WOFS_D1,
                                                   d1_b, buf1, nullptr, nullptr, nullptr, nullptr);
    bn_part_k<<<dim3(64, 16), 256>>>(buf1, 64, 16384);
    bn_fin_k<<<1, 64>>>(64, 1.f / 262144.f);
    // d2
    tconv3x3<true, false, 0><<<gT, 256, T_SMEM>>>(buf1, wh + WOFS_D2, wl + WOFS_D2,
                                                  d2_b, buf2, d1_g, d1_be, nullptr, nullptr);
    bn_part_k<<<dim3(64, 16), 256>>>(buf2, 64, 16384);
    bn_fin_k<<<1, 64>>>(64, 1.f / 262144.f);
    // d3
    tconv3x3<true, false, 0><<<gT, 256, T_SMEM>>>(buf2, wh + WOFS_D3, wl + WOFS_D3,
                                                  d3_b, buf1, d2_g, d2_be, nullptr, nullptr);
    bn_part_k<<<dim3(64, 16), 256>>>(buf1, 64, 16384);
    bn_fin_k<<<1, 64>>>(64, 1.f / 262144.f);
    // r = BN3 + ReLU -> output region
    bn_relu_out_k<<<EW, 256>>>(buf1, d3_g, d3_be, r_out);

    // output_map = conv7x7(r)
    conv7x7_k<<<dim3(8, 8, 16), dim3(16, 16)>>>(r_out, out_w, out_b, map_out);
}